// round 12
// baseline (speedup 1.0000x reference)
#include <cuda_runtime.h>
#include <math.h>

#define NB 8
#define NA 21504
#define NG 60
#define NC 15
#define BA (NB*NA)
#define NBG (NB*NG)
#define L0N 16384
#define L1N 20480
#define LOG4F 1.3862943611198906f
#define FULLM 0xffffffffu
#define NSEG 16     // 16 segments of 1344 anchors per (b,g) row
#define MAXFG 4800  // <= NBG * 10

// ---------------- static device scratch ----------------
__device__ float g_bx[BA], g_by[BA];
__device__ float g_a2[BA], g_b2[BA], g_c2[BA], g_d2s[BA], g_ld2[BA];
__device__ float g_obj[BA], g_S[BA];
__device__ float g_lc[NC*BA];                 // [c][b*A+a]
__device__ float2 g_ic[(size_t)NBG*NA];       // {iou, cost}
__device__ float g_gcx[NBG], g_gcy[NBG], g_ghw[NBG], g_ghh[NBG];
__device__ float g_ga1[NBG], g_gb1[NBG], g_gc1[NBG], g_gd1s[NBG], g_gld1[NBG];
__device__ int   g_gcls[NBG], g_gvalid[NBG];
__device__ float g_pt[NBG*NSEG*10];           // partial top-iou lists
__device__ float g_pc[NBG*NSEG*10];           // partial bot-cost lists
__device__ int   g_pi[NBG*NSEG*10];           // partial bot indices
__device__ float g_pv[NBG*NSEG*10];           // partial bot ious
__device__ int   g_cnt[BA];                   // per-anchor match count
__device__ int   g_mg[BA];
__device__ float g_miou[BA];
__device__ int   g_nfg;
__device__ int   g_fgl[MAXFG];
__device__ float g_acc[5];   // 0: sum(1-iou_m), 1: bce_obj, 2: bce_cls, 3: num_fg, 4: num_gts

// ---------------- deterministic pair cost (shared: k_cost & k_fgloss) ----------------
__device__ __forceinline__ void pair_cost(
    float ga, float gb, float gc, float gcx, float gcy, float gld1,
    float a2, float b2, float c2, float bx, float by, float lbase,
    float S, float lc, float pb, float pc,
    float& iou, float& cost)
{
    float Af = __fadd_rn(ga, a2);
    float Bf = __fadd_rn(gb, b2);
    float Cf = __fadd_rn(gc, c2);
    float dx = __fsub_rn(gcx, bx);
    float dy = __fsub_rn(gcy, by);
    float cc = __fmul_rn(Cf, Cf);
    float den = __fadd_rn(__fmaf_rn(Af, Bf, -cc), 1e-8f);
    float rden = __fdividef(1.f, den);
    float dx2 = __fmul_rn(dx, dx);
    float dy2 = __fmul_rn(dy, dy);
    float t1 = __fmul_rn(__fmul_rn(0.25f, __fmaf_rn(Af, dy2, __fmul_rn(Bf, dx2))), rden);
    float t2 = __fmul_rn(__fmul_rn(-0.5f, __fmul_rn(Cf, __fmul_rn(dx, dy))), rden);
    float t3 = __fmul_rn(0.5f, __fsub_rn(__logf(den), __fadd_rn(gld1, lbase)));
    float bd = fminf(fmaxf(__fadd_rn(__fadd_rn(t1, t2), t3), 1e-8f), 100.f);
    float q = fminf(fmaxf(__fsub_rn(1.f, __expf(-bd)), 1e-20f), 1.f);
    iou = __fsub_rn(1.f, __fmul_rn(q, __frsqrt_rn(q)));
    float base = __fadd_rn(__fadd_rn(__fadd_rn(S, lc), pb), pc);
    cost = __fmaf_rn(-3.f, __logf(__fadd_rn(iou, 1e-8f)), base);
}

// ---------------- K0: zero match state ----------------
__global__ void k_zero() {
    int i = blockIdx.x * blockDim.x + threadIdx.x;
    if (i < BA) g_cnt[i] = 0;
    if (i == 0) g_nfg = 0;
}

// ---------------- K1b: GT prep + zero accumulators (1 block) ----------------
__global__ void k_gt(const float* __restrict__ labels) {
    int t = threadIdx.x;
    if (t < 5) g_acc[t] = 0.f;
    __syncthreads();
    if (t >= NBG) return;
    const float* L = labels + (size_t)t * 6;
    float l0 = L[0], l1 = L[1], l2 = L[2], l3 = L[3], l4 = L[4], l5 = L[5];
    float sum = l0 + l1 + l2 + l3 + l4 + l5;
    int valid = (sum > 0.f) ? 1 : 0;
    float sn, cs; __sincosf(l5, &sn, &cs);
    float w2 = l3*l3/12.0f, h2 = l4*l4/12.0f;
    float a1 = w2*cs*cs + h2*sn*sn;
    float b1 = w2*sn*sn + h2*cs*cs;
    float c1 = (w2 - h2) * cs * sn;
    float d1 = fmaxf(a1*b1 - c1*c1, 0.f);
    float d1s = d1 * __frsqrt_rn(fmaxf(d1, 1e-30f));
    g_gcx[t] = l1; g_gcy[t] = l2;
    g_ghw[t] = 0.5f * l3; g_ghh[t] = 0.5f * l4;
    g_ga1[t] = a1; g_gb1[t] = b1; g_gc1[t] = c1;
    g_gd1s[t] = d1s;
    g_gld1[t] = __logf(fmaxf(d1s, 1e-35f));
    g_gcls[t] = (int)l0;
    g_gvalid[t] = valid;
    if (valid) atomicAdd(&g_acc[4], 1.f);
}

// ---------------- K1: decode anchors + fold Sum bce(obj, 0) ----------------
__global__ void k_decode(const float* __restrict__ o8,
                         const float* __restrict__ o16,
                         const float* __restrict__ o32) {
    int t = blockIdx.x * blockDim.x + threadIdx.x;
    int b = t / NA;
    int a = t - b * NA;
    const float* src; int hw, i; float st; int gx, gy;
    if (a < L0N)       { src = o8;  hw = 16384; i = a;        st = 8.f;  gx = i & 127; gy = i >> 7; }
    else if (a < L1N)  { src = o16; hw = 4096;  i = a - L0N;  st = 16.f; gx = i & 63;  gy = i >> 6; }
    else               { src = o32; hw = 1024;  i = a - L1N;  st = 32.f; gx = i & 31;  gy = i >> 5; }
    const float* p0 = src + (size_t)b * 21 * hw + i;
    float r0 = p0[0], r1 = p0[hw], r2 = p0[2*hw], r3 = p0[3*hw], r4 = p0[4*hw], r5 = p0[5*hw];
    float bx = (r0 + (float)gx) * st;
    float by = (r1 + (float)gy) * st;
    float bw = __expf(r2) * st;
    float bh = __expf(r3) * st;
    float sn, cs; __sincosf(r4, &sn, &cs);
    float w2 = bw * bw / 12.0f, h2 = bh * bh / 12.0f;
    float a2 = w2*cs*cs + h2*sn*sn;
    float b2 = w2*sn*sn + h2*cs*cs;
    float c2 = (w2 - h2) * cs * sn;
    float d2 = fmaxf(a2*b2 - c2*c2, 0.f);
    float d2s = d2 * __frsqrt_rn(fmaxf(d2, 1e-30f));
    g_bx[t] = bx; g_by[t] = by;
    g_a2[t] = a2; g_b2[t] = b2; g_c2[t] = c2;
    g_d2s[t] = d2s;
    g_ld2[t] = __logf(fmaxf(d2s, 1e-35f));
    g_obj[t] = r5;
    float so = __fdividef(1.f, 1.f + __expf(-r5));
    float S = 0.f;
    #pragma unroll
    for (int c = 0; c < NC; c++) {
        float x = p0[(6 + c) * hw];
        float sc = __fdividef(1.f, 1.f + __expf(-x));
        float q = sc * so;
        float p = q * __frsqrt_rn(fmaxf(q, 1e-30f));
        p = fminf(fmaxf(p, 1e-7f), 1.f - 1e-7f);
        float lg = __logf(1.f - p);
        float lp = __logf(p);
        S -= lg;
        g_lc[c * BA + t] = lg - lp;
    }
    g_S[t] = S;
    // fold obj BCE against target 0 (fg correction -x applied in k_fgloss)
    float lo = fmaxf(r5, 0.f) + __logf(1.f + __expf(-fabsf(r5)));
    #pragma unroll
    for (int o = 16; o > 0; o >>= 1) lo += __shfl_down_sync(FULLM, lo, o);
    __shared__ float sred[4];
    int w = threadIdx.x >> 5, lane = threadIdx.x & 31;
    if (lane == 0) sred[w] = lo;
    __syncthreads();
    if (threadIdx.x == 0)
        atomicAdd(&g_acc[1], sred[0] + sred[1] + sred[2] + sred[3]);
}

// ---------------- K2: ious + cost; warp-uniform non-cand fast path ----------------
__global__ void k_cost() {
    int b = blockIdx.x / 84;
    int tile = blockIdx.x - b * 84;
    int tid = threadIdx.x;
    int a0 = tile * 256 + 2 * tid;
    int t0 = b * NA + a0;
    __shared__ float s_cx[NG], s_cy[NG], s_hw[NG], s_hh[NG];
    __shared__ float s_a1[NG], s_b1[NG], s_c1[NG], s_ld1[NG];
    __shared__ int   s_cls[NG], s_val[NG];
    if (tid < NG) {
        int gi = b * NG + tid;
        int v = g_gvalid[gi];
        s_val[tid] = v;
        s_cx[tid] = v ? g_gcx[gi] : 3.0e9f;
        s_cy[tid] = v ? g_gcy[gi] : 3.0e9f;
        s_hw[tid] = g_ghw[gi]; s_hh[tid] = g_ghh[gi];
        s_a1[tid] = g_ga1[gi]; s_b1[tid] = g_gb1[gi];
        s_c1[tid] = g_gc1[gi]; s_ld1[tid] = g_gld1[gi];
        s_cls[tid] = g_gcls[gi];
    }
    __syncthreads();
    float st; int lvlbase, shx, mskx;
    if (a0 < L0N)      { st = 8.f;  lvlbase = 0;    shx = 7; mskx = 127; }
    else if (a0 < L1N) { st = 16.f; lvlbase = L0N;  shx = 6; mskx = 63; }
    else               { st = 32.f; lvlbase = L1N;  shx = 5; mskx = 31; }
    int i0 = a0 - lvlbase;
    float xc0 = ((float)(i0 & mskx) + 0.5f) * st;
    float yc0 = ((float)(i0 >> shx) + 0.5f) * st;
    float xc1 = xc0 + st;
    float rad = 2.5f * st;

    unsigned long long both0 = 0ULL, both1 = 0ULL;
    bool c0 = false, c1 = false;
    #pragma unroll 4
    for (int g = 0; g < NG; g++) {
        float cx = s_cx[g], cy = s_cy[g], hwv = s_hw[g], hh = s_hh[g];
        float dx0 = fabsf(xc0 - cx), dy0 = fabsf(yc0 - cy);
        float dx1 = fabsf(xc1 - cx);
        bool ib0 = (dx0 < hwv) & (dy0 < hh);
        bool ic0 = (dx0 < rad) & (dy0 < rad);
        bool ib1 = (dx1 < hwv) & (dy0 < hh);
        bool ic1 = (dx1 < rad) & (dy0 < rad);
        c0 |= ib0 | ic0; c1 |= ib1 | ic1;
        if (ib0 & ic0) both0 |= (1ULL << g);
        if (ib1 & ic1) both1 |= (1ULL << g);
    }
    size_t rowbase = (size_t)b * NG * NA + a0;
    unsigned anyc = __ballot_sync(FULLM, c0 | c1);
    if (anyc == 0u) {
        // whole warp non-cand: dummy stores only (non-cand never enters bottom-10,
        // contributes 0 to top-iou; penalty separation keeps ordering exact)
        for (int g = 0; g < NG; g++)
            if (s_val[g])
                *(float4*)(g_ic + rowbase + (size_t)g * NA) = make_float4(0.f, 2e9f, 0.f, 2e9f);
        return;
    }
    float2 bx01 = *(const float2*)&g_bx[t0];
    float2 by01 = *(const float2*)&g_by[t0];
    float2 A01  = *(const float2*)&g_a2[t0];
    float2 B01  = *(const float2*)&g_b2[t0];
    float2 C01  = *(const float2*)&g_c2[t0];
    float2 S01  = *(const float2*)&g_S[t0];
    float2 ld01 = *(const float2*)&g_ld2[t0];
    float lb0 = ld01.x + LOG4F, lb1 = ld01.y + LOG4F;
    float pc0 = c0 ? 0.f : 1e6f;
    float pc1 = c1 ? 0.f : 1e6f;

    for (int g = 0; g < NG; g++) {
        if (!s_val[g]) continue;
        float ga = s_a1[g], gb = s_b1[g], gc = s_c1[g];
        float cx = s_cx[g], cy = s_cy[g];
        float lg1 = s_ld1[g];
        float2 lc = *(const float2*)&g_lc[s_cls[g] * BA + t0];
        float4 o;
        float pb0 = ((both0 >> g) & 1ULL) ? 0.f : 1e5f;
        float pb1 = ((both1 >> g) & 1ULL) ? 0.f : 1e5f;
        pair_cost(ga, gb, gc, cx, cy, lg1, A01.x, B01.x, C01.x, bx01.x, by01.x,
                  lb0, S01.x, lc.x, pb0, pc0, o.x, o.y);
        pair_cost(ga, gb, gc, cx, cy, lg1, A01.y, B01.y, C01.y, bx01.y, by01.y,
                  lb1, S01.y, lc.y, pb1, pc1, o.z, o.w);
        *(float4*)(g_ic + rowbase + (size_t)g * NA) = o;
    }
}

// ---------------- selection helpers (warp-distributed lists, lanes 0..9) ----------------
__device__ __forceinline__ bool pless(float c1, int i1, float c2, int i2) {
    return (c1 < c2) || (c1 == c2 && i1 < i2);
}
__device__ __forceinline__ void wins_top(float& tv, int lane, float c) {
    unsigned bm = __ballot_sync(FULLM, (lane < 10) && (c > tv)) & 0x3FFu;
    if (bm) {
        int p = __ffs(bm) - 1;
        float up = __shfl_up_sync(FULLM, tv, 1);
        if (lane < 10 && lane >= p) tv = (lane == p) ? c : up;
    }
}
__device__ __forceinline__ void wins_bot3(float& bcv, int& biv, float& bov,
                                          int lane, float c, int i, float io) {
    unsigned bm = __ballot_sync(FULLM, (lane < 10) && pless(c, i, bcv, biv)) & 0x3FFu;
    if (bm) {
        int p = __ffs(bm) - 1;
        float uc = __shfl_up_sync(FULLM, bcv, 1);
        int   ui = __shfl_up_sync(FULLM, biv, 1);
        float uo = __shfl_up_sync(FULLM, bov, 1);
        if (lane < 10 && lane >= p) {
            bcv = (lane == p) ? c : uc;
            biv = (lane == p) ? i : ui;
            bov = (lane == p) ? io : uo;
        }
    }
}

// ---------------- K3a: per-(b,g,segment) partials (R10 loop + iou carry) ----------------
__global__ void k_sel1() {
    int bg = blockIdx.x >> 2;
    int part = blockIdx.x & 3;
    if (!g_gvalid[bg]) return;
    int w = threadIdx.x >> 5, lane = threadIdx.x & 31;
    int seg = part * 4 + w;
    const float4* __restrict__ row4 = (const float4*)(g_ic + (size_t)bg * NA);
    int base = seg * 672;

    float tv = 0.f; float bcv = 3.0e38f; int biv = 0x7fffffff; float bov = 0.f;
    float thr_t = 0.f; float thr_c = 3.0e38f; int thr_i = 0x7fffffff;

    float4 f0 = row4[base + lane];
    float4 f1 = row4[base + 32 + lane];
    #pragma unroll 1
    for (int s = 0; s < 21; s++) {
        float4 f2;
        if (s < 19) f2 = row4[base + (s + 2) * 32 + lane];
        int fi = base + s * 32 + lane;
        float e0 = (f0.y < 1e6f) ? f0.x : 0.f;
        float e1 = (f0.w < 1e6f) ? f0.z : 0.f;
        float em = fmaxf(e0, e1);
        float cm = fminf(f0.y, f0.w);
        bool need = (em > thr_t) | (cm <= thr_c);
        unsigned nb = __ballot_sync(FULLM, need);
        if (nb) {
            unsigned mt = __ballot_sync(FULLM, em > thr_t);
            unsigned mc = __ballot_sync(FULLM, (cm < thr_c) || (cm == thr_c && 2*fi <= thr_i));
            while (mt) {
                int src = __ffs(mt) - 1; mt &= mt - 1;
                wins_top(tv, lane, __shfl_sync(FULLM, e0, src));
                wins_top(tv, lane, __shfl_sync(FULLM, e1, src));
            }
            thr_t = __shfl_sync(FULLM, tv, 9);
            while (mc) {
                int src = __ffs(mc) - 1; mc &= mc - 1;
                int ab = 2 * (base + s * 32 + src);
                wins_bot3(bcv, biv, bov, lane,
                          __shfl_sync(FULLM, f0.y, src), ab, __shfl_sync(FULLM, f0.x, src));
                wins_bot3(bcv, biv, bov, lane,
                          __shfl_sync(FULLM, f0.w, src), ab + 1, __shfl_sync(FULLM, f0.z, src));
            }
            thr_c = __shfl_sync(FULLM, bcv, 9);
            thr_i = __shfl_sync(FULLM, biv, 9);
        }
        f0 = f1; f1 = f2;
    }
    if (lane < 10) {
        int o = (bg * NSEG + seg) * 10 + lane;
        g_pt[o] = tv; g_pc[o] = bcv; g_pi[o] = biv; g_pv[o] = bov;
    }
}

// ---------------- K3b: merge partials; dyn_k; scatter matched anchors ----------------
__global__ void k_sel2() {
    int bg = blockIdx.x;
    int lane = threadIdx.x;
    if (!g_gvalid[bg]) return;
    int b = bg / NG, g = bg - b * NG;
    const float* __restrict__ pt  = g_pt + (size_t)bg * NSEG * 10;
    const float* __restrict__ pcr = g_pc + (size_t)bg * NSEG * 10;
    const int*   __restrict__ pir = g_pi + (size_t)bg * NSEG * 10;
    const float* __restrict__ pvr = g_pv + (size_t)bg * NSEG * 10;

    float tv = 0.f, bcv = 3.0e38f, bov = 0.f; int biv = 0x7fffffff;
    float thr_t = 0.f, thr_c = 3.0e38f; int thr_i = 0x7fffffff;
    #pragma unroll
    for (int i = 0; i < 5; i++) {
        int e = i * 32 + lane;
        bool ok = e < NSEG * 10;
        float a = ok ? pt[e]  : 0.f;
        float c = ok ? pcr[e] : 3.0e38f;
        int  ix = ok ? pir[e] : 0x7fffffff;
        float io = ok ? pvr[e] : 0.f;
        unsigned mt = __ballot_sync(FULLM, a > thr_t);
        unsigned mc = __ballot_sync(FULLM, (c < thr_c) || (c == thr_c && ix < thr_i));
        while (mt) {
            int src = __ffs(mt) - 1; mt &= mt - 1;
            wins_top(tv, lane, __shfl_sync(FULLM, a, src));
        }
        thr_t = __shfl_sync(FULLM, tv, 9);
        while (mc) {
            int src = __ffs(mc) - 1; mc &= mc - 1;
            wins_bot3(bcv, biv, bov, lane,
                      __shfl_sync(FULLM, c, src), __shfl_sync(FULLM, ix, src),
                      __shfl_sync(FULLM, io, src));
        }
        thr_c = __shfl_sync(FULLM, bcv, 9);
        thr_i = __shfl_sync(FULLM, biv, 9);
    }
    float x = (lane < 10) ? tv : 0.f;
    #pragma unroll
    for (int o = 16; o > 0; o >>= 1) x += __shfl_xor_sync(FULLM, x, o);
    int k = (int)x;
    if (k < 1) k = 1;
    if (k > 10) k = 10;
    // matched anchors = first k entries of the sorted bottom list
    if (lane < k) {
        int t = b * NA + biv;
        int old = atomicAdd(&g_cnt[t], 1);
        if (old == 0) {
            g_mg[t] = g;
            g_miou[t] = bov;
            int pos = atomicAdd(&g_nfg, 1);
            g_fgl[pos] = t;
        }
    }
}

// ---------------- K5: losses over fg anchors only ----------------
__global__ void k_fgloss(const float* __restrict__ o8,
                         const float* __restrict__ o16,
                         const float* __restrict__ o32) {
    int i = blockIdx.x * blockDim.x + threadIdx.x;
    int nfg = g_nfg;
    float liou = 0.f, lcls = 0.f, lobjc = 0.f, fo = 0.f;
    if (i < nfg) {
        int t = g_fgl[i];
        int b = t / NA;
        int a = t - b * NA;
        int cnt = g_cnt[t];
        int mg; float pi;
        if (cnt == 1) { mg = g_mg[t]; pi = g_miou[t]; }
        else {
            // conflict: one-hot argmin over all valid g, bitwise-identical pair_cost
            float st; int lvlbase, shx, mskx;
            if (a < L0N)      { st = 8.f;  lvlbase = 0;    shx = 7; mskx = 127; }
            else if (a < L1N) { st = 16.f; lvlbase = L0N;  shx = 6; mskx = 63; }
            else              { st = 32.f; lvlbase = L1N;  shx = 5; mskx = 31; }
            int ii = a - lvlbase;
            float xc = ((float)(ii & mskx) + 0.5f) * st;
            float yc = ((float)(ii >> shx) + 0.5f) * st;
            float rad = 2.5f * st;
            float bx = g_bx[t], by = g_by[t];
            float a2 = g_a2[t], b2 = g_b2[t], c2 = g_c2[t];
            float S = g_S[t];
            float lbase = g_ld2[t] + LOG4F;
            float minc = 3.4e38f; mg = 0; pi = 0.f;
            for (int g = 0; g < NG; g++) {
                int gi = b * NG + g;
                if (!g_gvalid[gi]) continue;
                float gcx = g_gcx[gi], gcy = g_gcy[gi];
                float dxa = fabsf(xc - gcx), dya = fabsf(yc - gcy);
                bool ib = (dxa < g_ghw[gi]) & (dya < g_ghh[gi]);
                bool ic = (dxa < rad) & (dya < rad);
                float pb = (ib & ic) ? 0.f : 1e5f;
                float lc = g_lc[g_gcls[gi] * BA + t];
                float iou, cost;
                pair_cost(g_ga1[gi], g_gb1[gi], g_gc1[gi], gcx, gcy, g_gld1[gi],
                          a2, b2, c2, bx, by, lbase, S, lc, pb, 0.f, iou, cost);
                if (cost < minc) { minc = cost; mg = g; pi = iou; }
            }
        }
        int gi = b * NG + mg;
        // loss_iou: prob_iou(bbox, matched gt)
        {
            float bx = g_bx[t], by = g_by[t];
            float a2 = g_a2[t], b2 = g_b2[t], c2 = g_c2[t], d2s = g_d2s[t];
            float Af = a2 + g_ga1[gi], Bf = b2 + g_gb1[gi], Cf = c2 + g_gc1[gi];
            float dx = bx - g_gcx[gi], dy = by - g_gcy[gi];
            float den = Af * Bf - Cf * Cf + 1e-8f;
            float rden = __fdividef(1.f, den);
            float t1 = 0.25f * (Af*dy*dy + Bf*dx*dx) * rden;
            float t2 = -0.5f * Cf * dx * dy * rden;
            float t3 = 0.5f * __logf(__fdividef(den, 4.f * g_gd1s[gi] * d2s + 1e-8f));
            float bd = fminf(fmaxf(t1 + t2 + t3, 1e-8f), 100.f);
            float q = fminf(fmaxf(1.f - __expf(-bd), 1e-20f), 1.f);
            float ioum = 1.f - q * __frsqrt_rn(q);
            liou = 1.f - ioum;
        }
        // loss_cls
        {
            const float* src; int hw, idx;
            if (a < L0N)      { src = o8;  hw = 16384; idx = a; }
            else if (a < L1N) { src = o16; hw = 4096;  idx = a - L0N; }
            else              { src = o32; hw = 1024;  idx = a - L1N; }
            const float* pc = src + ((size_t)b * 21 + 6) * hw + idx;
            int mcls = g_gcls[gi];
            #pragma unroll
            for (int c = 0; c < NC; c++) {
                float x = pc[(size_t)c * hw];
                float tg = (c == mcls) ? pi : 0.f;
                lcls += fmaxf(x, 0.f) - x * tg + __logf(1.f + __expf(-fabsf(x)));
            }
        }
        lobjc = -g_obj[t];  // bce(x,1) - bce(x,0) = -x
        fo = 1.f;
    }
    #pragma unroll
    for (int o = 16; o > 0; o >>= 1) {
        liou  += __shfl_down_sync(FULLM, liou, o);
        lcls  += __shfl_down_sync(FULLM, lcls, o);
        lobjc += __shfl_down_sync(FULLM, lobjc, o);
        fo    += __shfl_down_sync(FULLM, fo, o);
    }
    if ((threadIdx.x & 31) == 0) {
        atomicAdd(&g_acc[0], liou);
        atomicAdd(&g_acc[1], lobjc);
        atomicAdd(&g_acc[2], lcls);
        atomicAdd(&g_acc[3], fo);
    }
}

// ---------------- K6: finalize ----------------
__global__ void k_final(float* __restrict__ out, int n) {
    if (threadIdx.x == 0) {
        float nfg = g_acc[3];
        float nf = fmaxf(nfg, 1.f);
        float liou = g_acc[0] / nf;
        float lobj = g_acc[1] / nf;
        float lcls = g_acc[2] / nf;
        float li5 = 5.f * liou;
        float loss = li5 + lobj + lcls;
        if (n > 0) out[0] = loss;
        if (n > 1) out[1] = li5;
        if (n > 2) out[2] = lobj;
        if (n > 3) out[3] = lcls;
        if (n > 4) out[4] = 0.f;
        if (n > 5) out[5] = nfg / fmaxf(g_acc[4], 1.f);
        for (int i = 6; i < n; i++) out[i] = 0.f;
    }
}

// ---------------- launch ----------------
extern "C" void kernel_launch(void* const* d_in, const int* in_sizes, int n_in,
                              void* d_out, int out_size) {
    const float* o8     = (const float*)d_in[0];
    const float* o16    = (const float*)d_in[1];
    const float* o32    = (const float*)d_in[2];
    const float* labels = (const float*)d_in[3];
    float* out = (float*)d_out;

    k_zero<<<(BA + 511) / 512, 512>>>();
    k_gt<<<1, 512>>>(labels);
    k_decode<<<BA / 128, 128>>>(o8, o16, o32);
    k_cost<<<NB * 84, 128>>>();
    k_sel1<<<NBG * 4, 128>>>();
    k_sel2<<<NBG, 32>>>();
    k_fgloss<<<(MAXFG + 127) / 128, 128>>>(o8, o16, o32);
    k_final<<<1, 32>>>(out, out_size);
}

// round 13
// speedup vs baseline: 1.0384x; 1.0384x over previous
#include <cuda_runtime.h>
#include <math.h>

#define NB 8
#define NA 21504
#define NG 60
#define NC 15
#define BA (NB*NA)
#define NBG (NB*NG)
#define L0N 16384
#define L1N 20480
#define LOG4F 1.3862943611198906f
#define FULLM 0xffffffffu
#define NSEG 16      // 16 segments of 1344 anchors per (b,g) row
#define MAXFG 4800
#define CINIT 990000.0f   // between max cand cost (~1.01e5) and min non-cand cost (~1.0999e6)

// ---------------- static device scratch ----------------
__device__ float g_bx[BA], g_by[BA];
__device__ float g_a2[BA], g_b2[BA], g_c2[BA], g_d2s[BA], g_ld2[BA];
__device__ float g_obj[BA], g_S[BA];
__device__ float g_lc[NC*BA];                 // [c][b*A+a]
__device__ float2 g_ic[(size_t)NBG*NA];       // {iou, cost}; non-cand entries are dummies
__device__ float g_gcx[NBG], g_gcy[NBG], g_ghw[NBG], g_ghh[NBG];
__device__ float g_ga1[NBG], g_gb1[NBG], g_gc1[NBG], g_gd1s[NBG], g_gld1[NBG];
__device__ int   g_gcls[NBG], g_gvalid[NBG];
__device__ float g_pt[NBG*NSEG*10];           // partial top-iou lists
__device__ float g_pc[NBG*NSEG*10];           // partial bot-cost lists
__device__ int   g_pi[NBG*NSEG*10];           // partial bot indices
__device__ float g_pv[NBG*NSEG*10];           // partial bot ious
__device__ int   g_cnt[BA];
__device__ int   g_mg[BA];
__device__ float g_miou[BA];
__device__ int   g_nfg;
__device__ int   g_done;
__device__ int   g_fgl[MAXFG];
__device__ float g_acc[5];   // 0: sum(1-iou_m), 1: bce_obj, 2: bce_cls, 3: num_fg, 4: num_gts

// ---------------- deterministic pair cost (shared: k_cost & k_fgloss) ----------------
__device__ __forceinline__ void pair_cost(
    float ga, float gb, float gc, float gcx, float gcy, float gld1,
    float a2, float b2, float c2, float bx, float by, float lbase,
    float S, float lc, float pb, float pc,
    float& iou, float& cost)
{
    float Af = __fadd_rn(ga, a2);
    float Bf = __fadd_rn(gb, b2);
    float Cf = __fadd_rn(gc, c2);
    float dx = __fsub_rn(gcx, bx);
    float dy = __fsub_rn(gcy, by);
    float cc = __fmul_rn(Cf, Cf);
    float den = __fadd_rn(__fmaf_rn(Af, Bf, -cc), 1e-8f);
    float rden = __fdividef(1.f, den);
    float dx2 = __fmul_rn(dx, dx);
    float dy2 = __fmul_rn(dy, dy);
    float t1 = __fmul_rn(__fmul_rn(0.25f, __fmaf_rn(Af, dy2, __fmul_rn(Bf, dx2))), rden);
    float t2 = __fmul_rn(__fmul_rn(-0.5f, __fmul_rn(Cf, __fmul_rn(dx, dy))), rden);
    float t3 = __fmul_rn(0.5f, __fsub_rn(__logf(den), __fadd_rn(gld1, lbase)));
    float bd = fminf(fmaxf(__fadd_rn(__fadd_rn(t1, t2), t3), 1e-8f), 100.f);
    float q = fminf(fmaxf(__fsub_rn(1.f, __expf(-bd)), 1e-20f), 1.f);
    iou = __fsub_rn(1.f, __fmul_rn(q, __frsqrt_rn(q)));
    float base = __fadd_rn(__fadd_rn(__fadd_rn(S, lc), pb), pc);
    cost = __fmaf_rn(-3.f, __logf(__fadd_rn(iou, 1e-8f)), base);
}

// ---------------- K1b: GT prep + zero accumulators (1 block) ----------------
__global__ void k_gt(const float* __restrict__ labels) {
    int t = threadIdx.x;
    if (t < 5) g_acc[t] = 0.f;
    if (t == 5) g_nfg = 0;
    if (t == 6) g_done = 0;
    __syncthreads();
    if (t >= NBG) return;
    const float* L = labels + (size_t)t * 6;
    float l0 = L[0], l1 = L[1], l2 = L[2], l3 = L[3], l4 = L[4], l5 = L[5];
    float sum = l0 + l1 + l2 + l3 + l4 + l5;
    int valid = (sum > 0.f) ? 1 : 0;
    float sn, cs; __sincosf(l5, &sn, &cs);
    float w2 = l3*l3/12.0f, h2 = l4*l4/12.0f;
    float a1 = w2*cs*cs + h2*sn*sn;
    float b1 = w2*sn*sn + h2*cs*cs;
    float c1 = (w2 - h2) * cs * sn;
    float d1 = fmaxf(a1*b1 - c1*c1, 0.f);
    float d1s = d1 * __frsqrt_rn(fmaxf(d1, 1e-30f));
    g_gcx[t] = l1; g_gcy[t] = l2;
    g_ghw[t] = 0.5f * l3; g_ghh[t] = 0.5f * l4;
    g_ga1[t] = a1; g_gb1[t] = b1; g_gc1[t] = c1;
    g_gd1s[t] = d1s;
    g_gld1[t] = __logf(fmaxf(d1s, 1e-35f));
    g_gcls[t] = (int)l0;
    g_gvalid[t] = valid;
    if (valid) atomicAdd(&g_acc[4], 1.f);
}

// ---------------- K1: decode + cnt zero + fold Sum bce(obj,0) ----------------
__global__ void k_decode(const float* __restrict__ o8,
                         const float* __restrict__ o16,
                         const float* __restrict__ o32) {
    int t = blockIdx.x * blockDim.x + threadIdx.x;
    int b = t / NA;
    int a = t - b * NA;
    g_cnt[t] = 0;
    const float* src; int hw, i; float st; int gx, gy;
    if (a < L0N)       { src = o8;  hw = 16384; i = a;        st = 8.f;  gx = i & 127; gy = i >> 7; }
    else if (a < L1N)  { src = o16; hw = 4096;  i = a - L0N;  st = 16.f; gx = i & 63;  gy = i >> 6; }
    else               { src = o32; hw = 1024;  i = a - L1N;  st = 32.f; gx = i & 31;  gy = i >> 5; }
    const float* p0 = src + (size_t)b * 21 * hw + i;
    float r0 = p0[0], r1 = p0[hw], r2 = p0[2*hw], r3 = p0[3*hw], r4 = p0[4*hw], r5 = p0[5*hw];
    float bx = (r0 + (float)gx) * st;
    float by = (r1 + (float)gy) * st;
    float bw = __expf(r2) * st;
    float bh = __expf(r3) * st;
    float sn, cs; __sincosf(r4, &sn, &cs);
    float w2 = bw * bw / 12.0f, h2 = bh * bh / 12.0f;
    float a2 = w2*cs*cs + h2*sn*sn;
    float b2 = w2*sn*sn + h2*cs*cs;
    float c2 = (w2 - h2) * cs * sn;
    float d2 = fmaxf(a2*b2 - c2*c2, 0.f);
    float d2s = d2 * __frsqrt_rn(fmaxf(d2, 1e-30f));
    g_bx[t] = bx; g_by[t] = by;
    g_a2[t] = a2; g_b2[t] = b2; g_c2[t] = c2;
    g_d2s[t] = d2s;
    g_ld2[t] = __logf(fmaxf(d2s, 1e-35f));
    g_obj[t] = r5;
    float so = __fdividef(1.f, 1.f + __expf(-r5));
    float S = 0.f;
    #pragma unroll
    for (int c = 0; c < NC; c++) {
        float x = p0[(6 + c) * hw];
        float sc = __fdividef(1.f, 1.f + __expf(-x));
        float q = sc * so;
        float p = q * __frsqrt_rn(fmaxf(q, 1e-30f));
        p = fminf(fmaxf(p, 1e-7f), 1.f - 1e-7f);
        float lg = __logf(1.f - p);
        float lp = __logf(p);
        S -= lg;
        g_lc[c * BA + t] = lg - lp;
    }
    g_S[t] = S;
    // obj BCE vs target 0 (fg correction -x applied in k_fgloss)
    float lo = fmaxf(r5, 0.f) + __logf(1.f + __expf(-fabsf(r5)));
    #pragma unroll
    for (int o = 16; o > 0; o >>= 1) lo += __shfl_down_sync(FULLM, lo, o);
    __shared__ float sred[4];
    int w = threadIdx.x >> 5, lane = threadIdx.x & 31;
    if (lane == 0) sred[w] = lo;
    __syncthreads();
    if (threadIdx.x == 0)
        atomicAdd(&g_acc[1], sred[0] + sred[1] + sred[2] + sred[3]);
}

// ---------------- K2: cost, 1 anchor/thread (occupancy), non-cand fast path ----------------
__global__ void k_cost() {
    int b = blockIdx.x / 168;                  // 168 blocks of 128 anchors per image
    int t = blockIdx.x * 128 + threadIdx.x;
    int a = t - b * NA;
    int tid = threadIdx.x;
    __shared__ float s_cx[NG], s_cy[NG], s_hw[NG], s_hh[NG];
    __shared__ float s_a1[NG], s_b1[NG], s_c1[NG], s_ld1[NG];
    __shared__ int   s_cls[NG], s_val[NG];
    if (tid < NG) {
        int gi = b * NG + tid;
        int v = g_gvalid[gi];
        s_val[tid] = v;
        s_cx[tid] = v ? g_gcx[gi] : 3.0e9f;
        s_cy[tid] = v ? g_gcy[gi] : 3.0e9f;
        s_hw[tid] = g_ghw[gi]; s_hh[tid] = g_ghh[gi];
        s_a1[tid] = g_ga1[gi]; s_b1[tid] = g_gb1[gi];
        s_c1[tid] = g_gc1[gi]; s_ld1[tid] = g_gld1[gi];
        s_cls[tid] = g_gcls[gi];
    }
    __syncthreads();
    float st; int lvlbase, shx, mskx;
    if (a < L0N)      { st = 8.f;  lvlbase = 0;    shx = 7; mskx = 127; }
    else if (a < L1N) { st = 16.f; lvlbase = L0N;  shx = 6; mskx = 63; }
    else              { st = 32.f; lvlbase = L1N;  shx = 5; mskx = 31; }
    int i0 = a - lvlbase;
    float xc = ((float)(i0 & mskx) + 0.5f) * st;
    float yc = ((float)(i0 >> shx) + 0.5f) * st;
    float rad = 2.5f * st;

    unsigned long long both = 0ULL;
    bool cand = false;
    #pragma unroll 4
    for (int g = 0; g < NG; g++) {
        float dx = fabsf(xc - s_cx[g]);
        float dy = fabsf(yc - s_cy[g]);
        bool ib = (dx < s_hw[g]) & (dy < s_hh[g]);
        bool ic = (dx < rad) & (dy < rad);
        cand |= ib | ic;
        if (ib & ic) both |= (1ULL << g);
    }
    size_t rowbase = (size_t)b * NG * NA + a;
    unsigned anyc = __ballot_sync(FULLM, cand);
    if (anyc == 0u) {
        // warp all non-cand: dummies (provably never consumed downstream)
        for (int g = 0; g < NG; g++)
            if (s_val[g]) g_ic[rowbase + (size_t)g * NA] = make_float2(0.f, 2e9f);
        return;
    }
    float bx = g_bx[t], by = g_by[t];
    float a2 = g_a2[t], b2 = g_b2[t], c2 = g_c2[t];
    float S = g_S[t];
    float lbase = g_ld2[t] + LOG4F;
    float pc = cand ? 0.f : 1e6f;

    for (int g = 0; g < NG; g++) {
        if (!s_val[g]) continue;
        float lc = g_lc[s_cls[g] * BA + t];
        float pb = ((both >> g) & 1ULL) ? 0.f : 1e5f;
        float iou, cost;
        pair_cost(s_a1[g], s_b1[g], s_c1[g], s_cx[g], s_cy[g], s_ld1[g],
                  a2, b2, c2, bx, by, lbase, S, lc, pb, pc, iou, cost);
        g_ic[rowbase + (size_t)g * NA] = make_float2(iou, cost);
    }
}

// ---------------- selection helpers (warp-distributed lists, lanes 0..9) ----------------
__device__ __forceinline__ bool pless(float c1, int i1, float c2, int i2) {
    return (c1 < c2) || (c1 == c2 && i1 < i2);
}
__device__ __forceinline__ void wins_top(float& tv, int lane, float c) {
    unsigned bm = __ballot_sync(FULLM, (lane < 10) && (c > tv)) & 0x3FFu;
    if (bm) {
        int p = __ffs(bm) - 1;
        float up = __shfl_up_sync(FULLM, tv, 1);
        if (lane < 10 && lane >= p) tv = (lane == p) ? c : up;
    }
}
__device__ __forceinline__ void wins_bot3(float& bcv, int& biv, float& bov,
                                          int lane, float c, int i, float io) {
    unsigned bm = __ballot_sync(FULLM, (lane < 10) && pless(c, i, bcv, biv)) & 0x3FFu;
    if (bm) {
        int p = __ffs(bm) - 1;
        float uc = __shfl_up_sync(FULLM, bcv, 1);
        int   ui = __shfl_up_sync(FULLM, biv, 1);
        float uo = __shfl_up_sync(FULLM, bov, 1);
        if (lane < 10 && lane >= p) {
            bcv = (lane == p) ? c : uc;
            biv = (lane == p) ? i : ui;
            bov = (lane == p) ? io : uo;
        }
    }
}

// ---------------- K3a: per-(b,g,segment) partials; CINIT kills non-cand fill ----------------
__global__ void k_sel1() {
    int bg = blockIdx.x >> 2;
    int part = blockIdx.x & 3;
    if (!g_gvalid[bg]) return;
    int w = threadIdx.x >> 5, lane = threadIdx.x & 31;
    int seg = part * 4 + w;
    const float4* __restrict__ row4 = (const float4*)(g_ic + (size_t)bg * NA);
    int base = seg * 672;

    float tv = 0.f; float bcv = CINIT; int biv = 0x7fffffff; float bov = 0.f;
    float thr_t = 0.f; float thr_c = CINIT; int thr_i = 0x7fffffff;

    float4 f0 = row4[base + lane];
    float4 f1 = row4[base + 32 + lane];
    #pragma unroll 1
    for (int s = 0; s < 21; s++) {
        float4 f2;
        if (s < 19) f2 = row4[base + (s + 2) * 32 + lane];
        int fi = base + s * 32 + lane;
        float e0 = (f0.y < 1e6f) ? f0.x : 0.f;   // cand <=> cost < 1e6 (margin >= 9e5)
        float e1 = (f0.w < 1e6f) ? f0.z : 0.f;
        float em = fmaxf(e0, e1);
        float cm = fminf(f0.y, f0.w);
        bool need = (em > thr_t) | (cm <= thr_c);
        unsigned nb = __ballot_sync(FULLM, need);
        if (nb) {
            unsigned mt = __ballot_sync(FULLM, em > thr_t);
            unsigned mc = __ballot_sync(FULLM, (cm < thr_c) || (cm == thr_c && 2*fi <= thr_i));
            while (mt) {
                int src = __ffs(mt) - 1; mt &= mt - 1;
                wins_top(tv, lane, __shfl_sync(FULLM, e0, src));
                wins_top(tv, lane, __shfl_sync(FULLM, e1, src));
            }
            thr_t = __shfl_sync(FULLM, tv, 9);
            while (mc) {
                int src = __ffs(mc) - 1; mc &= mc - 1;
                int ab = 2 * (base + s * 32 + src);
                wins_bot3(bcv, biv, bov, lane,
                          __shfl_sync(FULLM, f0.y, src), ab, __shfl_sync(FULLM, f0.x, src));
                wins_bot3(bcv, biv, bov, lane,
                          __shfl_sync(FULLM, f0.w, src), ab + 1, __shfl_sync(FULLM, f0.z, src));
            }
            thr_c = __shfl_sync(FULLM, bcv, 9);
            thr_i = __shfl_sync(FULLM, biv, 9);
        }
        f0 = f1; f1 = f2;
    }
    if (lane < 10) {
        int o = (bg * NSEG + seg) * 10 + lane;
        g_pt[o] = tv; g_pc[o] = bcv; g_pi[o] = biv; g_pv[o] = bov;
    }
}

// ---------------- K3b: merge partials; dyn_k; scatter matched anchors ----------------
__global__ void k_sel2() {
    int bg = blockIdx.x;
    int lane = threadIdx.x;
    if (!g_gvalid[bg]) return;
    int b = bg / NG, g = bg - b * NG;
    const float* __restrict__ pt  = g_pt + (size_t)bg * NSEG * 10;
    const float* __restrict__ pcr = g_pc + (size_t)bg * NSEG * 10;
    const int*   __restrict__ pir = g_pi + (size_t)bg * NSEG * 10;
    const float* __restrict__ pvr = g_pv + (size_t)bg * NSEG * 10;

    float tv = 0.f, bcv = CINIT, bov = 0.f; int biv = 0x7fffffff;
    float thr_t = 0.f, thr_c = CINIT; int thr_i = 0x7fffffff;
    #pragma unroll
    for (int i = 0; i < 5; i++) {
        int e = i * 32 + lane;
        bool ok = e < NSEG * 10;
        float a = ok ? pt[e]  : 0.f;
        float c = ok ? pcr[e] : 3.0e38f;
        int  ix = ok ? pir[e] : 0x7fffffff;
        float io = ok ? pvr[e] : 0.f;
        unsigned mt = __ballot_sync(FULLM, a > thr_t);
        unsigned mc = __ballot_sync(FULLM, (c < thr_c) || (c == thr_c && ix < thr_i));
        while (mt) {
            int src = __ffs(mt) - 1; mt &= mt - 1;
            wins_top(tv, lane, __shfl_sync(FULLM, a, src));
        }
        thr_t = __shfl_sync(FULLM, tv, 9);
        while (mc) {
            int src = __ffs(mc) - 1; mc &= mc - 1;
            wins_bot3(bcv, biv, bov, lane,
                      __shfl_sync(FULLM, c, src), __shfl_sync(FULLM, ix, src),
                      __shfl_sync(FULLM, io, src));
        }
        thr_c = __shfl_sync(FULLM, bcv, 9);
        thr_i = __shfl_sync(FULLM, biv, 9);
    }
    float x = (lane < 10) ? tv : 0.f;
    #pragma unroll
    for (int o = 16; o > 0; o >>= 1) x += __shfl_xor_sync(FULLM, x, o);
    int k = (int)x;
    if (k < 1) k = 1;
    if (k > 10) k = 10;
    if (lane < k) {
        int t = b * NA + biv;
        int old = atomicAdd(&g_cnt[t], 1);
        if (old == 0) {
            g_mg[t] = g;
            g_miou[t] = bov;
            int pos = atomicAdd(&g_nfg, 1);
            g_fgl[pos] = t;
        }
    }
}

// ---------------- K5: losses over fg anchors only + fused finalize ----------------
__global__ void k_fgloss(const float* __restrict__ o8,
                         const float* __restrict__ o16,
                         const float* __restrict__ o32,
                         float* __restrict__ out, int n) {
    int i = blockIdx.x * blockDim.x + threadIdx.x;
    int nfg = g_nfg;
    float liou = 0.f, lcls = 0.f, lobjc = 0.f, fo = 0.f;
    if (i < nfg) {
        int t = g_fgl[i];
        int b = t / NA;
        int a = t - b * NA;
        int cnt = g_cnt[t];
        int mg; float pi;
        if (cnt == 1) { mg = g_mg[t]; pi = g_miou[t]; }
        else {
            // conflict: argmin over valid g with bitwise-identical pair_cost
            float st; int lvlbase, shx, mskx;
            if (a < L0N)      { st = 8.f;  lvlbase = 0;    shx = 7; mskx = 127; }
            else if (a < L1N) { st = 16.f; lvlbase = L0N;  shx = 6; mskx = 63; }
            else              { st = 32.f; lvlbase = L1N;  shx = 5; mskx = 31; }
            int ii = a - lvlbase;
            float xc = ((float)(ii & mskx) + 0.5f) * st;
            float yc = ((float)(ii >> shx) + 0.5f) * st;
            float rad = 2.5f * st;
            float bx = g_bx[t], by = g_by[t];
            float a2 = g_a2[t], b2 = g_b2[t], c2 = g_c2[t];
            float S = g_S[t];
            float lbase = g_ld2[t] + LOG4F;
            float minc = 3.4e38f; mg = 0; pi = 0.f;
            for (int g = 0; g < NG; g++) {
                int gi = b * NG + g;
                if (!g_gvalid[gi]) continue;
                float gcx = g_gcx[gi], gcy = g_gcy[gi];
                float dxa = fabsf(xc - gcx), dya = fabsf(yc - gcy);
                bool ib = (dxa < g_ghw[gi]) & (dya < g_ghh[gi]);
                bool ic = (dxa < rad) & (dya < rad);
                float pb = (ib & ic) ? 0.f : 1e5f;
                float lc = g_lc[g_gcls[gi] * BA + t];
                float iou, cost;
                pair_cost(g_ga1[gi], g_gb1[gi], g_gc1[gi], gcx, gcy, g_gld1[gi],
                          a2, b2, c2, bx, by, lbase, S, lc, pb, 0.f, iou, cost);
                if (cost < minc) { minc = cost; mg = g; pi = iou; }
            }
        }
        int gi = b * NG + mg;
        {
            float bx = g_bx[t], by = g_by[t];
            float a2 = g_a2[t], b2 = g_b2[t], c2 = g_c2[t], d2s = g_d2s[t];
            float Af = a2 + g_ga1[gi], Bf = b2 + g_gb1[gi], Cf = c2 + g_gc1[gi];
            float dx = bx - g_gcx[gi], dy = by - g_gcy[gi];
            float den = Af * Bf - Cf * Cf + 1e-8f;
            float rden = __fdividef(1.f, den);
            float t1 = 0.25f * (Af*dy*dy + Bf*dx*dx) * rden;
            float t2 = -0.5f * Cf * dx * dy * rden;
            float t3 = 0.5f * __logf(__fdividef(den, 4.f * g_gd1s[gi] * d2s + 1e-8f));
            float bd = fminf(fmaxf(t1 + t2 + t3, 1e-8f), 100.f);
            float q = fminf(fmaxf(1.f - __expf(-bd), 1e-20f), 1.f);
            float ioum = 1.f - q * __frsqrt_rn(q);
            liou = 1.f - ioum;
        }
        {
            const float* src; int hw, idx;
            if (a < L0N)      { src = o8;  hw = 16384; idx = a; }
            else if (a < L1N) { src = o16; hw = 4096;  idx = a - L0N; }
            else              { src = o32; hw = 1024;  idx = a - L1N; }
            const float* pc = src + ((size_t)b * 21 + 6) * hw + idx;
            int mcls = g_gcls[gi];
            #pragma unroll
            for (int c = 0; c < NC; c++) {
                float x = pc[(size_t)c * hw];
                float tg = (c == mcls) ? pi : 0.f;
                lcls += fmaxf(x, 0.f) - x * tg + __logf(1.f + __expf(-fabsf(x)));
            }
        }
        lobjc = -g_obj[t];   // bce(x,1) - bce(x,0) = -x
        fo = 1.f;
    }
    #pragma unroll
    for (int o = 16; o > 0; o >>= 1) {
        liou  += __shfl_down_sync(FULLM, liou, o);
        lcls  += __shfl_down_sync(FULLM, lcls, o);
        lobjc += __shfl_down_sync(FULLM, lobjc, o);
        fo    += __shfl_down_sync(FULLM, fo, o);
    }
    if ((threadIdx.x & 31) == 0) {
        atomicAdd(&g_acc[0], liou);
        atomicAdd(&g_acc[1], lobjc);
        atomicAdd(&g_acc[2], lcls);
        atomicAdd(&g_acc[3], fo);
    }
    // finalize in last-finishing block
    __syncthreads();
    if (threadIdx.x == 0) {
        __threadfence();
        int prev = atomicAdd(&g_done, 1);
        if (prev == gridDim.x - 1) {
            float nf2 = g_acc[3];
            float nf = fmaxf(nf2, 1.f);
            float li = g_acc[0] / nf;
            float lo = g_acc[1] / nf;
            float lc2 = g_acc[2] / nf;
            float li5 = 5.f * li;
            if (n > 0) out[0] = li5 + lo + lc2;
            if (n > 1) out[1] = li5;
            if (n > 2) out[2] = lo;
            if (n > 3) out[3] = lc2;
            if (n > 4) out[4] = 0.f;
            if (n > 5) out[5] = nf2 / fmaxf(g_acc[4], 1.f);
            for (int j = 6; j < n; j++) out[j] = 0.f;
        }
    }
}

// ---------------- launch ----------------
extern "C" void kernel_launch(void* const* d_in, const int* in_sizes, int n_in,
                              void* d_out, int out_size) {
    const float* o8     = (const float*)d_in[0];
    const float* o16    = (const float*)d_in[1];
    const float* o32    = (const float*)d_in[2];
    const float* labels = (const float*)d_in[3];
    float* out = (float*)d_out;

    k_gt<<<1, 512>>>(labels);
    k_decode<<<BA / 128, 128>>>(o8, o16, o32);
    k_cost<<<BA / 128, 128>>>();
    k_sel1<<<NBG * 4, 128>>>();
    k_sel2<<<NBG, 32>>>();
    k_fgloss<<<(MAXFG + 127) / 128, 128>>>(o8, o16, o32, out, out_size);
}

// round 14
// speedup vs baseline: 1.2052x; 1.1607x over previous
#include <cuda_runtime.h>
#include <math.h>

#define NB 8
#define NA 21504
#define NG 60
#define NC 15
#define BA (NB*NA)
#define NBG (NB*NG)
#define L0N 16384
#define L1N 20480
#define LOG4F 1.3862943611198906f
#define FULLM 0xffffffffu
#define NSEG 16
#define MAXFG 4800
#define CINIT 990000.0f   // between max cand cost (~1.01e5) and any sentinel

// ---------------- static device scratch ----------------
__device__ float g_bx[BA], g_by[BA];
__device__ float g_a2[BA], g_b2[BA], g_c2[BA], g_d2s[BA], g_ld2[BA];
__device__ float g_obj[BA], g_S[BA];
__device__ float g_lc[NC*BA];                 // [c][b*A+a]
__device__ float2 g_ic[(size_t)NBG*NA];       // compacted {iou, cost}: [bg][slot]
__device__ int   g_ci[BA];                    // compacted cand anchor idx: [b][slot]
__device__ int   g_ccnt[NB];                  // cand count per image
__device__ float g_gcx[NBG], g_gcy[NBG], g_ghw[NBG], g_ghh[NBG];
__device__ float g_ga1[NBG], g_gb1[NBG], g_gc1[NBG], g_gd1s[NBG], g_gld1[NBG];
__device__ int   g_gcls[NBG], g_gvalid[NBG];
__device__ float g_pt[NBG*NSEG*10];
__device__ float g_pc[NBG*NSEG*10];
__device__ int   g_pi[NBG*NSEG*10];
__device__ float g_pv[NBG*NSEG*10];
__device__ int   g_cnt[BA];
__device__ int   g_mg[BA];
__device__ float g_miou[BA];
__device__ int   g_nfg;
__device__ int   g_done;
__device__ int   g_fgl[MAXFG];
__device__ float g_acc[5];   // 0: sum(1-iou_m), 1: bce_obj, 2: bce_cls, 3: num_fg, 4: num_gts

// ---------------- deterministic pair cost (shared: k_cost & k_fgloss) ----------------
__device__ __forceinline__ void pair_cost(
    float ga, float gb, float gc, float gcx, float gcy, float gld1,
    float a2, float b2, float c2, float bx, float by, float lbase,
    float S, float lc, float pb, float pc,
    float& iou, float& cost)
{
    float Af = __fadd_rn(ga, a2);
    float Bf = __fadd_rn(gb, b2);
    float Cf = __fadd_rn(gc, c2);
    float dx = __fsub_rn(gcx, bx);
    float dy = __fsub_rn(gcy, by);
    float cc = __fmul_rn(Cf, Cf);
    float den = __fadd_rn(__fmaf_rn(Af, Bf, -cc), 1e-8f);
    float rden = __fdividef(1.f, den);
    float dx2 = __fmul_rn(dx, dx);
    float dy2 = __fmul_rn(dy, dy);
    float t1 = __fmul_rn(__fmul_rn(0.25f, __fmaf_rn(Af, dy2, __fmul_rn(Bf, dx2))), rden);
    float t2 = __fmul_rn(__fmul_rn(-0.5f, __fmul_rn(Cf, __fmul_rn(dx, dy))), rden);
    float t3 = __fmul_rn(0.5f, __fsub_rn(__logf(den), __fadd_rn(gld1, lbase)));
    float bd = fminf(fmaxf(__fadd_rn(__fadd_rn(t1, t2), t3), 1e-8f), 100.f);
    float q = fminf(fmaxf(__fsub_rn(1.f, __expf(-bd)), 1e-20f), 1.f);
    iou = __fsub_rn(1.f, __fmul_rn(q, __frsqrt_rn(q)));
    float base = __fadd_rn(__fadd_rn(__fadd_rn(S, lc), pb), pc);
    cost = __fmaf_rn(-3.f, __logf(__fadd_rn(iou, 1e-8f)), base);
}

// ---------------- K1b: GT prep + zero accumulators (1 block) ----------------
__global__ void k_gt(const float* __restrict__ labels) {
    int t = threadIdx.x;
    if (t < 5) g_acc[t] = 0.f;
    if (t == 5) g_nfg = 0;
    if (t == 6) g_done = 0;
    if (t >= 8 && t < 8 + NB) g_ccnt[t - 8] = 0;
    __syncthreads();
    if (t >= NBG) return;
    const float* L = labels + (size_t)t * 6;
    float l0 = L[0], l1 = L[1], l2 = L[2], l3 = L[3], l4 = L[4], l5 = L[5];
    float sum = l0 + l1 + l2 + l3 + l4 + l5;
    int valid = (sum > 0.f) ? 1 : 0;
    float sn, cs; __sincosf(l5, &sn, &cs);
    float w2 = l3*l3/12.0f, h2 = l4*l4/12.0f;
    float a1 = w2*cs*cs + h2*sn*sn;
    float b1 = w2*sn*sn + h2*cs*cs;
    float c1 = (w2 - h2) * cs * sn;
    float d1 = fmaxf(a1*b1 - c1*c1, 0.f);
    float d1s = d1 * __frsqrt_rn(fmaxf(d1, 1e-30f));
    g_gcx[t] = l1; g_gcy[t] = l2;
    g_ghw[t] = 0.5f * l3; g_ghh[t] = 0.5f * l4;
    g_ga1[t] = a1; g_gb1[t] = b1; g_gc1[t] = c1;
    g_gd1s[t] = d1s;
    g_gld1[t] = __logf(fmaxf(d1s, 1e-35f));
    g_gcls[t] = (int)l0;
    g_gvalid[t] = valid;
    if (valid) atomicAdd(&g_acc[4], 1.f);
}

// ---------------- K1: decode + cnt zero + fold Sum bce(obj,0) ----------------
__global__ void k_decode(const float* __restrict__ o8,
                         const float* __restrict__ o16,
                         const float* __restrict__ o32) {
    int t = blockIdx.x * blockDim.x + threadIdx.x;
    int b = t / NA;
    int a = t - b * NA;
    g_cnt[t] = 0;
    const float* src; int hw, i; float st; int gx, gy;
    if (a < L0N)       { src = o8;  hw = 16384; i = a;        st = 8.f;  gx = i & 127; gy = i >> 7; }
    else if (a < L1N)  { src = o16; hw = 4096;  i = a - L0N;  st = 16.f; gx = i & 63;  gy = i >> 6; }
    else               { src = o32; hw = 1024;  i = a - L1N;  st = 32.f; gx = i & 31;  gy = i >> 5; }
    const float* p0 = src + (size_t)b * 21 * hw + i;
    float r0 = p0[0], r1 = p0[hw], r2 = p0[2*hw], r3 = p0[3*hw], r4 = p0[4*hw], r5 = p0[5*hw];
    float bx = (r0 + (float)gx) * st;
    float by = (r1 + (float)gy) * st;
    float bw = __expf(r2) * st;
    float bh = __expf(r3) * st;
    float sn, cs; __sincosf(r4, &sn, &cs);
    float w2 = bw * bw / 12.0f, h2 = bh * bh / 12.0f;
    float a2 = w2*cs*cs + h2*sn*sn;
    float b2 = w2*sn*sn + h2*cs*cs;
    float c2 = (w2 - h2) * cs * sn;
    float d2 = fmaxf(a2*b2 - c2*c2, 0.f);
    float d2s = d2 * __frsqrt_rn(fmaxf(d2, 1e-30f));
    g_bx[t] = bx; g_by[t] = by;
    g_a2[t] = a2; g_b2[t] = b2; g_c2[t] = c2;
    g_d2s[t] = d2s;
    g_ld2[t] = __logf(fmaxf(d2s, 1e-35f));
    g_obj[t] = r5;
    float so = __fdividef(1.f, 1.f + __expf(-r5));
    float S = 0.f;
    #pragma unroll
    for (int c = 0; c < NC; c++) {
        float x = p0[(6 + c) * hw];
        float sc = __fdividef(1.f, 1.f + __expf(-x));
        float q = sc * so;
        float p = q * __frsqrt_rn(fmaxf(q, 1e-30f));
        p = fminf(fmaxf(p, 1e-7f), 1.f - 1e-7f);
        float lg = __logf(1.f - p);
        float lp = __logf(p);
        S -= lg;
        g_lc[c * BA + t] = lg - lp;
    }
    g_S[t] = S;
    float lo = fmaxf(r5, 0.f) + __logf(1.f + __expf(-fabsf(r5)));
    #pragma unroll
    for (int o = 16; o > 0; o >>= 1) lo += __shfl_down_sync(FULLM, lo, o);
    __shared__ float sred[4];
    int w = threadIdx.x >> 5, lane = threadIdx.x & 31;
    if (lane == 0) sred[w] = lo;
    __syncthreads();
    if (threadIdx.x == 0)
        atomicAdd(&g_acc[1], sred[0] + sred[1] + sred[2] + sred[3]);
}

// ---------------- K2: cand compaction + cost for cand anchors only ----------------
__global__ void k_cost() {
    int b = blockIdx.x / 168;
    int t = blockIdx.x * 128 + threadIdx.x;
    int a = t - b * NA;
    int tid = threadIdx.x;
    int lane = tid & 31;
    __shared__ float s_cx[NG], s_cy[NG], s_hw[NG], s_hh[NG];
    __shared__ float s_a1[NG], s_b1[NG], s_c1[NG], s_ld1[NG];
    __shared__ int   s_cls[NG], s_val[NG];
    if (tid < NG) {
        int gi = b * NG + tid;
        int v = g_gvalid[gi];
        s_val[tid] = v;
        s_cx[tid] = v ? g_gcx[gi] : 3.0e9f;
        s_cy[tid] = v ? g_gcy[gi] : 3.0e9f;
        s_hw[tid] = g_ghw[gi]; s_hh[tid] = g_ghh[gi];
        s_a1[tid] = g_ga1[gi]; s_b1[tid] = g_gb1[gi];
        s_c1[tid] = g_gc1[gi]; s_ld1[tid] = g_gld1[gi];
        s_cls[tid] = g_gcls[gi];
    }
    __syncthreads();
    float st; int lvlbase, shx, mskx;
    if (a < L0N)      { st = 8.f;  lvlbase = 0;    shx = 7; mskx = 127; }
    else if (a < L1N) { st = 16.f; lvlbase = L0N;  shx = 6; mskx = 63; }
    else              { st = 32.f; lvlbase = L1N;  shx = 5; mskx = 31; }
    int i0 = a - lvlbase;
    float xc = ((float)(i0 & mskx) + 0.5f) * st;
    float yc = ((float)(i0 >> shx) + 0.5f) * st;
    float rad = 2.5f * st;

    unsigned long long both = 0ULL;
    bool cand = false;
    #pragma unroll 4
    for (int g = 0; g < NG; g++) {
        float dx = fabsf(xc - s_cx[g]);
        float dy = fabsf(yc - s_cy[g]);
        bool ib = (dx < s_hw[g]) & (dy < s_hh[g]);
        bool ic = (dx < rad) & (dy < rad);
        cand |= ib | ic;
        if (ib & ic) both |= (1ULL << g);
    }
    unsigned mask = __ballot_sync(FULLM, cand);
    if (mask == 0u) return;                 // warp all non-cand: nothing stored
    int base;
    if (lane == 0) base = atomicAdd(&g_ccnt[b], __popc(mask));
    base = __shfl_sync(FULLM, base, 0);
    if (!cand) return;
    int slot = base + __popc(mask & ((1u << lane) - 1u));
    g_ci[b * NA + slot] = a;

    float bx = g_bx[t], by = g_by[t];
    float a2 = g_a2[t], b2 = g_b2[t], c2 = g_c2[t];
    float S = g_S[t];
    float lbase = g_ld2[t] + LOG4F;
    size_t rowbase = (size_t)b * NG * NA + slot;

    for (int g = 0; g < NG; g++) {
        if (!s_val[g]) continue;
        float lc = g_lc[s_cls[g] * BA + t];
        float pb = ((both >> g) & 1ULL) ? 0.f : 1e5f;
        float iou, cost;
        pair_cost(s_a1[g], s_b1[g], s_c1[g], s_cx[g], s_cy[g], s_ld1[g],
                  a2, b2, c2, bx, by, lbase, S, lc, pb, 0.f, iou, cost);
        g_ic[rowbase + (size_t)g * NA] = make_float2(iou, cost);
    }
}

// ---------------- selection helpers (warp-distributed lists, lanes 0..9) ----------------
__device__ __forceinline__ bool pless(float c1, int i1, float c2, int i2) {
    return (c1 < c2) || (c1 == c2 && i1 < i2);
}
__device__ __forceinline__ void wins_top(float& tv, int lane, float c) {
    unsigned bm = __ballot_sync(FULLM, (lane < 10) && (c > tv)) & 0x3FFu;
    if (bm) {
        int p = __ffs(bm) - 1;
        float up = __shfl_up_sync(FULLM, tv, 1);
        if (lane < 10 && lane >= p) tv = (lane == p) ? c : up;
    }
}
__device__ __forceinline__ void wins_bot3(float& bcv, int& biv, float& bov,
                                          int lane, float c, int i, float io) {
    unsigned bm = __ballot_sync(FULLM, (lane < 10) && pless(c, i, bcv, biv)) & 0x3FFu;
    if (bm) {
        int p = __ffs(bm) - 1;
        float uc = __shfl_up_sync(FULLM, bcv, 1);
        int   ui = __shfl_up_sync(FULLM, biv, 1);
        float uo = __shfl_up_sync(FULLM, bov, 1);
        if (lane < 10 && lane >= p) {
            bcv = (lane == p) ? c : uc;
            biv = (lane == p) ? i : ui;
            bov = (lane == p) ? io : uo;
        }
    }
}

// ---------------- K3a: per-(b,g,segment) partials over compacted cand list ----------------
__global__ void k_sel1() {
    int bg = blockIdx.x >> 2;
    int part = blockIdx.x & 3;
    if (!g_gvalid[bg]) return;
    int w = threadIdx.x >> 5, lane = threadIdx.x & 31;
    int seg = part * 4 + w;
    int b = bg / NG;
    int cnt = g_ccnt[b];
    const float2* __restrict__ row = g_ic + (size_t)bg * NA;
    const int* __restrict__ ci = g_ci + b * NA;

    float tv = 0.f; float bcv = CINIT; int biv = 0x7fffffff; float bov = 0.f;
    float thr_t = 0.f; float thr_c = CINIT; int thr_i = 0x7fffffff;

    for (int it = 0; it * (NSEG * 32) + seg * 32 < cnt; it++) {
        int slot = it * (NSEG * 32) + seg * 32 + lane;
        bool ok = slot < cnt;
        float2 f = make_float2(0.f, 3.0e38f);
        int idx = 0x7fffffff;
        if (ok) { f = row[slot]; idx = ci[slot]; }
        float e = ok ? f.x : 0.f;
        float c = ok ? f.y : 3.0e38f;
        bool need = (e > thr_t) | (c < thr_c) | ((c == thr_c) & (idx <= thr_i));
        unsigned nb = __ballot_sync(FULLM, need);
        if (nb) {
            unsigned mt = __ballot_sync(FULLM, e > thr_t);
            unsigned mc = __ballot_sync(FULLM, (c < thr_c) || (c == thr_c && idx <= thr_i));
            while (mt) {
                int src = __ffs(mt) - 1; mt &= mt - 1;
                wins_top(tv, lane, __shfl_sync(FULLM, e, src));
            }
            thr_t = __shfl_sync(FULLM, tv, 9);
            while (mc) {
                int src = __ffs(mc) - 1; mc &= mc - 1;
                wins_bot3(bcv, biv, bov, lane,
                          __shfl_sync(FULLM, c, src), __shfl_sync(FULLM, idx, src),
                          __shfl_sync(FULLM, e, src));
            }
            thr_c = __shfl_sync(FULLM, bcv, 9);
            thr_i = __shfl_sync(FULLM, biv, 9);
        }
    }
    if (lane < 10) {
        int o = (bg * NSEG + seg) * 10 + lane;
        g_pt[o] = tv; g_pc[o] = bcv; g_pi[o] = biv; g_pv[o] = bov;
    }
}

// ---------------- K3b: merge partials; dyn_k; scatter matched anchors ----------------
__global__ void k_sel2() {
    int bg = blockIdx.x;
    int lane = threadIdx.x;
    if (!g_gvalid[bg]) return;
    int b = bg / NG, g = bg - b * NG;
    const float* __restrict__ pt  = g_pt + (size_t)bg * NSEG * 10;
    const float* __restrict__ pcr = g_pc + (size_t)bg * NSEG * 10;
    const int*   __restrict__ pir = g_pi + (size_t)bg * NSEG * 10;
    const float* __restrict__ pvr = g_pv + (size_t)bg * NSEG * 10;

    float tv = 0.f, bcv = CINIT, bov = 0.f; int biv = 0x7fffffff;
    float thr_t = 0.f, thr_c = CINIT; int thr_i = 0x7fffffff;
    #pragma unroll
    for (int i = 0; i < 5; i++) {
        int e = i * 32 + lane;
        bool ok = e < NSEG * 10;
        float a = ok ? pt[e]  : 0.f;
        float c = ok ? pcr[e] : 3.0e38f;
        int  ix = ok ? pir[e] : 0x7fffffff;
        float io = ok ? pvr[e] : 0.f;
        unsigned mt = __ballot_sync(FULLM, a > thr_t);
        unsigned mc = __ballot_sync(FULLM, (c < thr_c) || (c == thr_c && ix < thr_i));
        while (mt) {
            int src = __ffs(mt) - 1; mt &= mt - 1;
            wins_top(tv, lane, __shfl_sync(FULLM, a, src));
        }
        thr_t = __shfl_sync(FULLM, tv, 9);
        while (mc) {
            int src = __ffs(mc) - 1; mc &= mc - 1;
            wins_bot3(bcv, biv, bov, lane,
                      __shfl_sync(FULLM, c, src), __shfl_sync(FULLM, ix, src),
                      __shfl_sync(FULLM, io, src));
        }
        thr_c = __shfl_sync(FULLM, bcv, 9);
        thr_i = __shfl_sync(FULLM, biv, 9);
    }
    float x = (lane < 10) ? tv : 0.f;
    #pragma unroll
    for (int o = 16; o > 0; o >>= 1) x += __shfl_xor_sync(FULLM, x, o);
    int k = (int)x;
    if (k < 1) k = 1;
    if (k > 10) k = 10;
    if (lane < k) {
        int t = b * NA + biv;
        int old = atomicAdd(&g_cnt[t], 1);
        if (old == 0) {
            g_mg[t] = g;
            g_miou[t] = bov;
            int pos = atomicAdd(&g_nfg, 1);
            g_fgl[pos] = t;
        }
    }
}

// ---------------- K5: losses over fg anchors only + fused finalize ----------------
__global__ void k_fgloss(const float* __restrict__ o8,
                         const float* __restrict__ o16,
                         const float* __restrict__ o32,
                         float* __restrict__ out, int n) {
    int i = blockIdx.x * blockDim.x + threadIdx.x;
    int nfg = g_nfg;
    float liou = 0.f, lcls = 0.f, lobjc = 0.f, fo = 0.f;
    if (i < nfg) {
        int t = g_fgl[i];
        int b = t / NA;
        int a = t - b * NA;
        int cnt = g_cnt[t];
        int mg; float pi;
        if (cnt == 1) { mg = g_mg[t]; pi = g_miou[t]; }
        else {
            float st; int lvlbase, shx, mskx;
            if (a < L0N)      { st = 8.f;  lvlbase = 0;    shx = 7; mskx = 127; }
            else if (a < L1N) { st = 16.f; lvlbase = L0N;  shx = 6; mskx = 63; }
            else              { st = 32.f; lvlbase = L1N;  shx = 5; mskx = 31; }
            int ii = a - lvlbase;
            float xc = ((float)(ii & mskx) + 0.5f) * st;
            float yc = ((float)(ii >> shx) + 0.5f) * st;
            float rad = 2.5f * st;
            float bx = g_bx[t], by = g_by[t];
            float a2 = g_a2[t], b2 = g_b2[t], c2 = g_c2[t];
            float S = g_S[t];
            float lbase = g_ld2[t] + LOG4F;
            float minc = 3.4e38f; mg = 0; pi = 0.f;
            for (int g = 0; g < NG; g++) {
                int gi = b * NG + g;
                if (!g_gvalid[gi]) continue;
                float gcx = g_gcx[gi], gcy = g_gcy[gi];
                float dxa = fabsf(xc - gcx), dya = fabsf(yc - gcy);
                bool ib = (dxa < g_ghw[gi]) & (dya < g_ghh[gi]);
                bool ic = (dxa < rad) & (dya < rad);
                float pb = (ib & ic) ? 0.f : 1e5f;
                float lc = g_lc[g_gcls[gi] * BA + t];
                float iou, cost;
                pair_cost(g_ga1[gi], g_gb1[gi], g_gc1[gi], gcx, gcy, g_gld1[gi],
                          a2, b2, c2, bx, by, lbase, S, lc, pb, 0.f, iou, cost);
                if (cost < minc) { minc = cost; mg = g; pi = iou; }
            }
        }
        int gi = b * NG + mg;
        {
            float bx = g_bx[t], by = g_by[t];
            float a2 = g_a2[t], b2 = g_b2[t], c2 = g_c2[t], d2s = g_d2s[t];
            float Af = a2 + g_ga1[gi], Bf = b2 + g_gb1[gi], Cf = c2 + g_gc1[gi];
            float dx = bx - g_gcx[gi], dy = by - g_gcy[gi];
            float den = Af * Bf - Cf * Cf + 1e-8f;
            float rden = __fdividef(1.f, den);
            float t1 = 0.25f * (Af*dy*dy + Bf*dx*dx) * rden;
            float t2 = -0.5f * Cf * dx * dy * rden;
            float t3 = 0.5f * __logf(__fdividef(den, 4.f * g_gd1s[gi] * d2s + 1e-8f));
            float bd = fminf(fmaxf(t1 + t2 + t3, 1e-8f), 100.f);
            float q = fminf(fmaxf(1.f - __expf(-bd), 1e-20f), 1.f);
            float ioum = 1.f - q * __frsqrt_rn(q);
            liou = 1.f - ioum;
        }
        {
            const float* src; int hw, idx;
            if (a < L0N)      { src = o8;  hw = 16384; idx = a; }
            else if (a < L1N) { src = o16; hw = 4096;  idx = a - L0N; }
            else              { src = o32; hw = 1024;  idx = a - L1N; }
            const float* pc = src + ((size_t)b * 21 + 6) * hw + idx;
            int mcls = g_gcls[gi];
            #pragma unroll
            for (int c = 0; c < NC; c++) {
                float x = pc[(size_t)c * hw];
                float tg = (c == mcls) ? pi : 0.f;
                lcls += fmaxf(x, 0.f) - x * tg + __logf(1.f + __expf(-fabsf(x)));
            }
        }
        lobjc = -g_obj[t];
        fo = 1.f;
    }
    #pragma unroll
    for (int o = 16; o > 0; o >>= 1) {
        liou  += __shfl_down_sync(FULLM, liou, o);
        lcls  += __shfl_down_sync(FULLM, lcls, o);
        lobjc += __shfl_down_sync(FULLM, lobjc, o);
        fo    += __shfl_down_sync(FULLM, fo, o);
    }
    if ((threadIdx.x & 31) == 0) {
        atomicAdd(&g_acc[0], liou);
        atomicAdd(&g_acc[1], lobjc);
        atomicAdd(&g_acc[2], lcls);
        atomicAdd(&g_acc[3], fo);
    }
    __syncthreads();
    if (threadIdx.x == 0) {
        __threadfence();
        int prev = atomicAdd(&g_done, 1);
        if (prev == gridDim.x - 1) {
            float nf2 = g_acc[3];
            float nf = fmaxf(nf2, 1.f);
            float li = g_acc[0] / nf;
            float lo = g_acc[1] / nf;
            float lc2 = g_acc[2] / nf;
            float li5 = 5.f * li;
            if (n > 0) out[0] = li5 + lo + lc2;
            if (n > 1) out[1] = li5;
            if (n > 2) out[2] = lo;
            if (n > 3) out[3] = lc2;
            if (n > 4) out[4] = 0.f;
            if (n > 5) out[5] = nf2 / fmaxf(g_acc[4], 1.f);
            for (int j = 6; j < n; j++) out[j] = 0.f;
        }
    }
}

// ---------------- launch ----------------
extern "C" void kernel_launch(void* const* d_in, const int* in_sizes, int n_in,
                              void* d_out, int out_size) {
    const float* o8     = (const float*)d_in[0];
    const float* o16    = (const float*)d_in[1];
    const float* o32    = (const float*)d_in[2];
    const float* labels = (const float*)d_in[3];
    float* out = (float*)d_out;

    k_gt<<<1, 512>>>(labels);
    k_decode<<<BA / 128, 128>>>(o8, o16, o32);
    k_cost<<<BA / 128, 128>>>();
    k_sel1<<<NBG * 4, 128>>>();
    k_sel2<<<NBG, 32>>>();
    k_fgloss<<<(MAXFG + 127) / 128, 128>>>(o8, o16, o32, out, out_size);
}